// round 14
// baseline (speedup 1.0000x reference)
#include <cuda_runtime.h>
#include <cuda_fp16.h>
#include <math.h>
#include <stdint.h>

#define N_ROIS      2000
#define MPAD        2048
#define POOL        7
#define C_FEAT      256
#define KDIM        (C_FEAT * POOL * POOL)   // 12544
#define K1I         (2 * KDIM)
#define HID         1024
#define K2I         (2 * HID)
#define NUM_CLASSES 81
#define NBOX        (NUM_CLASSES * 4)
#define NHEAD       (NUM_CLASSES + NBOX)     // 405
#define NHEADP      512
#define BN_EPS      0.001f
#define IMG_DIM     1024.0f

// prep kernel block layout
#define PB_POOL     N_ROIS
#define NB_CW1      192
#define NB_CW2      24
#define NB_CW3      12
#define NB_BN       10
#define PB_CW1      (PB_POOL)
#define PB_CW2      (PB_CW1 + NB_CW1)
#define PB_CW3      (PB_CW2 + NB_CW2)
#define PB_BN       (PB_CW3 + NB_CW3)
#define PREP_GRID   (PB_BN + NB_BN)

// ---------------- scratch (device globals; zero-initialized) ---------------
__device__ __align__(128) __half g_A1[(size_t)MPAD * K1I];
__device__ __align__(128) __half g_B1[(size_t)HID * KDIM];
__device__ __align__(128) __half g_A2[(size_t)MPAD * K2I];
__device__ __align__(128) __half g_B2[(size_t)HID * HID];
__device__ __align__(128) __half g_A3[(size_t)MPAD * K2I];
__device__ __align__(128) __half g_W3[(size_t)NHEADP * HID];
__device__ float g_scale1[HID], g_shift1[HID];
__device__ float g_scale2[HID], g_shift2[HID];
__device__ float g_shift3[NHEADP];

// ---------------- helpers ---------------------------------------------------
__device__ __forceinline__ uint32_t smem_u32(const void* p) {
    uint32_t a;
    asm("{ .reg .u64 t; cvta.to.shared.u64 t, %1; cvt.u32.u64 %0, t; }" : "=r"(a) : "l"(p));
    return a;
}
__device__ __forceinline__ void split_fp16(float v, __half& h, __half& l) {
    h = __float2half_rn(v);
    l = __float2half_rn(v - __half2float(h));
}
__device__ __forceinline__ void cp16(uint32_t sa, const void* ga) {
    asm volatile("cp.async.cg.shared.global [%0], [%1], 16;" :: "r"(sa), "l"(ga));
}
__device__ __forceinline__ void cp_commit() {
    asm volatile("cp.async.commit_group;" ::: "memory");
}
__device__ __forceinline__ void cp_wait1() {
    asm volatile("cp.async.wait_group 1;" ::: "memory");
}
__device__ __forceinline__ void ldsm_x4(uint32_t& r0, uint32_t& r1, uint32_t& r2, uint32_t& r3,
                                        uint32_t addr) {
    asm volatile("ldmatrix.sync.aligned.m8n8.x4.shared.b16 {%0,%1,%2,%3}, [%4];"
                 : "=r"(r0), "=r"(r1), "=r"(r2), "=r"(r3) : "r"(addr));
}
__device__ __forceinline__ void mma_fp16(float* d, const uint32_t* a, const uint32_t* b) {
    asm volatile(
        "mma.sync.aligned.m16n8k16.row.col.f32.f16.f16.f32 "
        "{%0,%1,%2,%3}, {%4,%5,%6,%7}, {%8,%9}, {%0,%1,%2,%3};"
        : "+f"(d[0]), "+f"(d[1]), "+f"(d[2]), "+f"(d[3])
        : "r"(a[0]), "r"(a[1]), "r"(a[2]), "r"(a[3]), "r"(b[0]), "r"(b[1]));
}
__device__ __forceinline__ int ioff(int k) { return ((k >> 4) << 5) + (k & 15); }

// ---- vectorized hi-only weight convert ------------------------------------
__device__ __forceinline__ void convw_unit(const float* __restrict__ W,
                                           __half* __restrict__ out,
                                           int K, long u)
{
    int kb16 = K >> 4;
    int n = (int)(u / kb16);
    int kb = (int)(u % kb16);
    const float4* src = reinterpret_cast<const float4*>(W + (size_t)n * K + (size_t)kb * 16);
    __half h[16];
#pragma unroll
    for (int q = 0; q < 4; q++) {
        float4 f = src[q];
        h[q * 4 + 0] = __float2half_rn(f.x);
        h[q * 4 + 1] = __float2half_rn(f.y);
        h[q * 4 + 2] = __float2half_rn(f.z);
        h[q * 4 + 3] = __float2half_rn(f.w);
    }
    uint4* d4 = reinterpret_cast<uint4*>(out + (size_t)n * K + (size_t)kb * 16);
    d4[0] = *reinterpret_cast<uint4*>(&h[0]);
    d4[1] = *reinterpret_cast<uint4*>(&h[8]);
}

// ---------------- mega prep: pool + weight converts + bn fold --------------
__global__ __launch_bounds__(256)
void prep_kernel(const float* __restrict__ p2, const float* __restrict__ p3,
                 const float* __restrict__ p4, const float* __restrict__ p5,
                 const float* __restrict__ rois,
                 const float* __restrict__ conv1_w, const float* __restrict__ conv2_w,
                 const float* __restrict__ logits_w, const float* __restrict__ bbox_w,
                 const float* __restrict__ cb1, const float* __restrict__ g1,
                 const float* __restrict__ b1, const float* __restrict__ m1,
                 const float* __restrict__ v1,
                 const float* __restrict__ cb2, const float* __restrict__ g2,
                 const float* __restrict__ b2, const float* __restrict__ m2,
                 const float* __restrict__ v2,
                 const float* __restrict__ lb, const float* __restrict__ bb)
{
    int bid = blockIdx.x;
    int tid = threadIdx.x;

    if (bid < PB_POOL) {
        int n = bid;
        float x1 = rois[4 * n + 0];
        float y1 = rois[4 * n + 1];
        float x2 = rois[4 * n + 2];
        float y2 = rois[4 * n + 3];

        float area = (y2 - y1) * (x2 - x1);
        float lv = rintf(log2f(sqrtf(area) / 224.0f)) + 4.0f;
        lv = fminf(fmaxf(lv, 2.0f), 5.0f);
        int lvl = (int)lv;

        const float* fmap;
        int H;
        if (lvl == 2)      { fmap = p2; H = 256; }
        else if (lvl == 3) { fmap = p3; H = 128; }
        else if (lvl == 4) { fmap = p4; H = 64;  }
        else               { fmap = p5; H = 32;  }

        float ny1 = y1 / IMG_DIM, nx1 = x1 / IMG_DIM;
        float ny2 = y2 / IMG_DIM, nx2 = x2 / IMG_DIM;

        __shared__ float s_ly[POOL], s_lx[POOL];
        __shared__ int   s_y0[POOL], s_y1[POOL], s_x0[POOL], s_x1[POOL];

        if (tid < POOL) {
            int i = tid;
            float t = (float)i / (float)(POOL - 1);
            float Hm1 = (float)(H - 1);
            float ys = ny1 * Hm1 + t * ((ny2 - ny1) * Hm1);
            float y0 = floorf(ys);
            s_ly[i] = ys - y0;
            int y0i = min(max((int)y0, 0), H - 1);
            s_y0[i] = y0i;
            s_y1[i] = min(y0i + 1, H - 1);
        } else if (tid < 2 * POOL) {
            int i = tid - POOL;
            float t = (float)i / (float)(POOL - 1);
            float Wm1 = (float)(H - 1);
            float xs = nx1 * Wm1 + t * ((nx2 - nx1) * Wm1);
            float x0 = floorf(xs);
            s_lx[i] = xs - x0;
            int x0i = min(max((int)x0, 0), H - 1);
            s_x0[i] = x0i;
            s_x1[i] = min(x0i + 1, H - 1);
        }
        __syncthreads();

        int HW = H * H;
        __half* arow = g_A1 + (size_t)n * K1I;

        // 4 consecutive k per thread: all in one 16-block, vector writes
        for (int base = tid * 4; base < KDIM; base += 1024) {
            __half hh[4], ll[4];
#pragma unroll
            for (int e = 0; e < 4; e++) {
                int idx = base + e;
                int c  = idx / (POOL * POOL);
                int p  = idx % (POOL * POOL);
                int iy = p / POOL;
                int ix = p % POOL;
                const float* f = fmap + (size_t)c * HW;
                int y0 = s_y0[iy], y1i = s_y1[iy];
                int x0 = s_x0[ix], x1i = s_x1[ix];
                float fy = s_ly[iy], fx = s_lx[ix];
                float v00 = __ldg(&f[y0  * H + x0 ]);
                float v01 = __ldg(&f[y0  * H + x1i]);
                float v10 = __ldg(&f[y1i * H + x0 ]);
                float v11 = __ldg(&f[y1i * H + x1i]);
                float v = v00 * (1.f - fy) * (1.f - fx)
                        + v01 * (1.f - fy) * fx
                        + v10 * fy * (1.f - fx)
                        + v11 * fy * fx;
                split_fp16(v, hh[e], ll[e]);
            }
            int o = ioff(base);   // base%16 in {0,4,8,12} -> 4 elems same block
            *reinterpret_cast<uint2*>(&arow[o])      = *reinterpret_cast<uint2*>(hh);
            *reinterpret_cast<uint2*>(&arow[o + 16]) = *reinterpret_cast<uint2*>(ll);
        }
    } else if (bid < PB_CW2) {
        long units = (long)HID * (KDIM >> 4);
        long start = (long)(bid - PB_CW1) * 256 + tid;
        long stride = (long)NB_CW1 * 256;
        for (long u = start; u < units; u += stride)
            convw_unit(conv1_w, g_B1, KDIM, u);
    } else if (bid < PB_CW3) {
        long units = (long)HID * (HID >> 4);
        long start = (long)(bid - PB_CW2) * 256 + tid;
        long stride = (long)NB_CW2 * 256;
        for (long u = start; u < units; u += stride)
            convw_unit(conv2_w, g_B2, HID, u);
    } else if (bid < PB_BN) {
        long units = (long)NHEAD * (HID >> 4);
        long start = (long)(bid - PB_CW3) * 256 + tid;
        long stride = (long)NB_CW3 * 256;
        int kb16 = HID >> 4;
        for (long u = start; u < units; u += stride) {
            int r = (int)(u / kb16);
            long uu = u % kb16;
            if (r < NUM_CLASSES)
                convw_unit(logits_w, g_W3, HID, (long)r * kb16 + uu);
            else
                convw_unit(bbox_w, g_W3 + (size_t)NUM_CLASSES * HID, HID,
                           (long)(r - NUM_CLASSES) * kb16 + uu);
        }
    } else {
        int i = (bid - PB_BN) * 256 + tid;
        if (i < HID) {
            float s = g1[i] * rsqrtf(v1[i] + BN_EPS);
            g_scale1[i] = s;
            g_shift1[i] = (cb1[i] - m1[i]) * s + b1[i];
        } else if (i < 2 * HID) {
            int j = i - HID;
            float s = g2[j] * rsqrtf(v2[j] + BN_EPS);
            g_scale2[j] = s;
            g_shift2[j] = (cb2[j] - m2[j]) * s + b2[j];
        } else if (i < 2 * HID + NHEADP) {
            int j = i - 2 * HID;
            float v = 0.f;
            if (j < NUM_CLASSES)      v = lb[j];
            else if (j < NHEAD)       v = bb[j - NUM_CLASSES];
            g_shift3[j] = v;
        }
    }
}

// ---------------- fp16 HMMA GEMM, 2-pass comp, 3-stage ring ----------------
// Templated on M-tile (128: 4x2 warps; 64: 2x4 warps). N tile fixed 128.
// Iter = 16 logical k. A stage MT*64B; B stage 4KB.
__device__ __forceinline__ uint32_t sw_a(int row, int ch) {      // 64B rows
    return (uint32_t)(row * 64 + ((ch ^ ((row >> 1) & 3)) << 4));
}
__device__ __forceinline__ uint32_t sw_b(int row, int ch) {      // 32B rows
    return (uint32_t)(row * 32 + ((ch ^ ((row >> 2) & 1)) << 4));
}

template<int MT>
__device__ __forceinline__ void load_stage(uint32_t stg, const __half* A, const __half* B,
                                           int m0, int n0, int ldA, int K, int it, int tid)
{
    // A: MT*4 chunks of 16B
#pragma unroll
    for (int j = 0; j < MT / 64; j++) {
        int u = tid + j * 256;
        int row = u >> 2;
        int ch = u & 3;
        cp16(stg + sw_a(row, ch),
             (const void*)(A + (size_t)(m0 + row) * ldA + it * 32 + ch * 8));
    }
    // B: 256 chunks of 16B
    {
        int row = tid >> 1;
        int ch = tid & 1;
        cp16(stg + MT * 64 + sw_b(row, ch),
             (const void*)(B + (size_t)(n0 + row) * K + it * 16 + ch * 8));
    }
}

// mode 1: fp16 split out rows of K2I; mode 2: head -> d_out
template<int MT>
__global__ __launch_bounds__(256)
void gemm_hmma_kernel(const __half* __restrict__ A, const __half* __restrict__ B,
                      int K,
                      const float* __restrict__ scale, const float* __restrict__ shift,
                      float* __restrict__ Cf, __half* __restrict__ Cb, int mode)
{
    constexpr int WM = MT / 32;          // m-warps (4 or 2)
    constexpr int WN = 8 / WM;           // n-warps (2 or 4)
    constexpr int WCOLS = 128 / WN;      // cols per warp (64 or 32)
    constexpr int NT = WCOLS / 16;       // b ldsm tiles (4 or 2)
    constexpr int NJ = WCOLS / 8;        // mma n-frags (8 or 4)
    constexpr int STG = MT * 64 + 4096;  // stage bytes (12KB or 8KB)

    __shared__ __align__(1024) uint8_t smem[3 * STG];

    int tid = threadIdx.x;
    int lane = tid & 31;
    int wid = tid >> 5;
    int wm = wid % WM;
    int wn = wid / WM;
    int m0 = blockIdx.y * MT;
    int n0 = blockIdx.x * 128;
    int ldA = 2 * K;

    uint32_t sb = smem_u32(smem);

    float acc[2][NJ][4];
#pragma unroll
    for (int i = 0; i < 2; i++)
#pragma unroll
        for (int j = 0; j < NJ; j++)
#pragma unroll
            for (int q = 0; q < 4; q++) acc[i][j][q] = 0.f;

    int nk = K / 16;

    load_stage<MT>(sb, A, B, m0, n0, ldA, K, 0, tid);
    cp_commit();
    load_stage<MT>(sb + STG, A, B, m0, n0, ldA, K, 1, tid);
    cp_commit();

    int arow = wm * 32 + (lane & 15);
    int ach  = lane >> 4;
    int brow = wn * WCOLS + (lane & 7) + ((lane & 16) ? 8 : 0);
    int bch  = (lane & 8) ? 1 : 0;

    uint32_t stg_of[3] = { sb, sb + STG, sb + 2u * STG };

    for (int i = 0; i < nk; i++) {
        cp_wait1();
        __syncthreads();
        int j = i + 2;
        if (j < nk)
            load_stage<MT>(stg_of[j % 3], A, B, m0, n0, ldA, K, j, tid);
        cp_commit();

        uint32_t st = stg_of[i % 3];
        uint32_t ah[2][4], al[2][4], bh[NJ][2];
#pragma unroll
        for (int mi = 0; mi < 2; mi++) {
            ldsm_x4(ah[mi][0], ah[mi][1], ah[mi][2], ah[mi][3],
                    st + sw_a(arow + mi * 16, ach));
            ldsm_x4(al[mi][0], al[mi][1], al[mi][2], al[mi][3],
                    st + sw_a(arow + mi * 16, ach + 2));
        }
#pragma unroll
        for (int nt = 0; nt < NT; nt++)
            ldsm_x4(bh[nt * 2][0], bh[nt * 2][1], bh[nt * 2 + 1][0], bh[nt * 2 + 1][1],
                    st + MT * 64 + sw_b(brow + nt * 16, bch));
#pragma unroll
        for (int mi = 0; mi < 2; mi++)
#pragma unroll
            for (int nj = 0; nj < NJ; nj++)
                mma_fp16(acc[mi][nj], ah[mi], bh[nj]);
#pragma unroll
        for (int mi = 0; mi < 2; mi++)
#pragma unroll
            for (int nj = 0; nj < NJ; nj++)
                mma_fp16(acc[mi][nj], al[mi], bh[nj]);
        __syncthreads();
    }

#pragma unroll
    for (int mi = 0; mi < 2; mi++) {
        int rbase = m0 + wm * 32 + mi * 16 + (lane >> 2);
#pragma unroll
        for (int nj = 0; nj < NJ; nj++) {
            int c = n0 + wn * WCOLS + nj * 8 + (lane & 3) * 2;
#pragma unroll
            for (int half = 0; half < 2; half++) {
                int m = rbase + half * 8;
                if (m >= N_ROIS) continue;
                if (mode == 1) {
                    float v0 = fmaxf(acc[mi][nj][half * 2 + 0] * scale[c]     + shift[c],     0.f);
                    float v1 = fmaxf(acc[mi][nj][half * 2 + 1] * scale[c + 1] + shift[c + 1], 0.f);
                    __half h0, l0, h1, l1;
                    split_fp16(v0, h0, l0);
                    split_fp16(v1, h1, l1);
                    __half2 hh; hh.x = h0; hh.y = h1;
                    __half2 ll; ll.x = l0; ll.y = l1;
                    __half* crow = Cb + (size_t)m * K2I + ioff(c);
                    *reinterpret_cast<__half2*>(&crow[0])  = hh;
                    *reinterpret_cast<__half2*>(&crow[16]) = ll;
                } else {
#pragma unroll
                    for (int e = 0; e < 2; e++) {
                        int col = c + e;
                        if (col >= NHEAD) continue;
                        float v = acc[mi][nj][half * 2 + e] + shift[col];
                        if (col < NUM_CLASSES)
                            Cf[(size_t)m * NUM_CLASSES + col] = v;
                        else
                            Cf[(size_t)(2 * N_ROIS * NUM_CLASSES) +
                               (size_t)m * NBOX + (col - NUM_CLASSES)] = v;
                    }
                }
            }
        }
    }
}

// ---------------- softmax over logits -> probs -----------------------------
__global__ __launch_bounds__(128)
void softmax_kernel(float* __restrict__ out)
{
    int roi = blockIdx.x * 4 + (threadIdx.x >> 5);
    int lane = threadIdx.x & 31;
    if (roi >= N_ROIS) return;
    const float* lg = out + (size_t)roi * NUM_CLASSES;
    float* pr = out + (size_t)N_ROIS * NUM_CLASSES + (size_t)roi * NUM_CLASSES;

    float mx = -INFINITY;
    for (int k = lane; k < NUM_CLASSES; k += 32) mx = fmaxf(mx, lg[k]);
#pragma unroll
    for (int off = 16; off > 0; off >>= 1)
        mx = fmaxf(mx, __shfl_xor_sync(0xFFFFFFFFu, mx, off));

    float s = 0.f;
    for (int k = lane; k < NUM_CLASSES; k += 32) s += expf(lg[k] - mx);
#pragma unroll
    for (int off = 16; off > 0; off >>= 1)
        s += __shfl_xor_sync(0xFFFFFFFFu, s, off);

    float inv = 1.f / s;
    for (int k = lane; k < NUM_CLASSES; k += 32)
        pr[k] = expf(lg[k] - mx) * inv;
}

// ---------------- launch ---------------------------------------------------
extern "C" void kernel_launch(void* const* d_in, const int* in_sizes, int n_in,
                              void* d_out, int out_size)
{
    const float* p2       = (const float*)d_in[0];
    const float* p3       = (const float*)d_in[1];
    const float* p4       = (const float*)d_in[2];
    const float* p5       = (const float*)d_in[3];
    const float* rois     = (const float*)d_in[4];
    const float* conv1_w  = (const float*)d_in[5];
    const float* conv1_b  = (const float*)d_in[6];
    const float* bn1_g    = (const float*)d_in[7];
    const float* bn1_b    = (const float*)d_in[8];
    const float* bn1_m    = (const float*)d_in[9];
    const float* bn1_v    = (const float*)d_in[10];
    const float* conv2_w  = (const float*)d_in[11];
    const float* conv2_b  = (const float*)d_in[12];
    const float* bn2_g    = (const float*)d_in[13];
    const float* bn2_b    = (const float*)d_in[14];
    const float* bn2_m    = (const float*)d_in[15];
    const float* bn2_v    = (const float*)d_in[16];
    const float* logits_w = (const float*)d_in[17];
    const float* logits_b = (const float*)d_in[18];
    const float* bbox_w   = (const float*)d_in[19];
    const float* bbox_b   = (const float*)d_in[20];
    float* out = (float*)d_out;

    __half *a1, *b1, *a2, *b2, *a3, *w3;
    float *sc1, *sf1, *sc2, *sf2, *sf3;
    cudaGetSymbolAddress((void**)&a1, g_A1);
    cudaGetSymbolAddress((void**)&b1, g_B1);
    cudaGetSymbolAddress((void**)&a2, g_A2);
    cudaGetSymbolAddress((void**)&b2, g_B2);
    cudaGetSymbolAddress((void**)&a3, g_A3);
    cudaGetSymbolAddress((void**)&w3, g_W3);
    cudaGetSymbolAddress((void**)&sc1, g_scale1);
    cudaGetSymbolAddress((void**)&sf1, g_shift1);
    cudaGetSymbolAddress((void**)&sc2, g_scale2);
    cudaGetSymbolAddress((void**)&sf2, g_shift2);
    cudaGetSymbolAddress((void**)&sf3, g_shift3);

    prep_kernel<<<PREP_GRID, 256>>>(p2, p3, p4, p5, rois,
                                    conv1_w, conv2_w, logits_w, bbox_w,
                                    conv1_b, bn1_g, bn1_b, bn1_m, bn1_v,
                                    conv2_b, bn2_g, bn2_b, bn2_m, bn2_v,
                                    logits_b, bbox_b);

    {
        dim3 grid1(HID / 128, MPAD / 128);       // (8, 16)
        gemm_hmma_kernel<128><<<grid1, 256>>>(a1, b1, KDIM, sc1, sf1, nullptr, a2, 1);
        dim3 grid2(HID / 128, MPAD / 64);        // (8, 32)
        gemm_hmma_kernel<64><<<grid2, 256>>>(a2, b2, HID, sc2, sf2, nullptr, a3, 1);
        dim3 grid3(NHEADP / 128, MPAD / 64);     // (4, 32)
        gemm_hmma_kernel<64><<<grid3, 256>>>(a3, w3, HID, nullptr, sf3, out, nullptr, 2);
    }

    softmax_kernel<<<(N_ROIS + 3) / 4, 128>>>(out);
}

// round 16
// speedup vs baseline: 1.0914x; 1.0914x over previous
#include <cuda_runtime.h>
#include <cuda_fp16.h>
#include <math.h>
#include <stdint.h>

#define N_ROIS      2000
#define MPAD        2048
#define POOL        7
#define C_FEAT      256
#define KDIM        (C_FEAT * POOL * POOL)   // 12544
#define K1I         (2 * KDIM)
#define HID         1024
#define K2I         (2 * HID)
#define NUM_CLASSES 81
#define NBOX        (NUM_CLASSES * 4)
#define NHEAD       (NUM_CLASSES + NBOX)     // 405
#define NHEADP      512
#define BN_EPS      0.001f
#define IMG_DIM     1024.0f

// prep kernel block layout
#define PB_POOL     N_ROIS
#define NB_CW1      192
#define NB_CW2      24
#define NB_CW3      12
#define NB_BN       10
#define PB_CW1      (PB_POOL)
#define PB_CW2      (PB_CW1 + NB_CW1)
#define PB_CW3      (PB_CW2 + NB_CW2)
#define PB_BN       (PB_CW3 + NB_CW3)
#define PREP_GRID   (PB_BN + NB_BN)

// ---------------- scratch (device globals; zero-initialized) ---------------
__device__ __align__(128) __half g_A1[(size_t)MPAD * K1I];
__device__ __align__(128) __half g_B1[(size_t)HID * KDIM];
__device__ __align__(128) __half g_A2[(size_t)MPAD * K2I];
__device__ __align__(128) __half g_B2[(size_t)HID * HID];
__device__ __align__(128) __half g_A3[(size_t)MPAD * K2I];
__device__ __align__(128) __half g_W3[(size_t)NHEADP * HID];
__device__ float g_scale1[HID], g_shift1[HID];
__device__ float g_scale2[HID], g_shift2[HID];
__device__ float g_shift3[NHEADP];

// ---------------- helpers ---------------------------------------------------
__device__ __forceinline__ uint32_t smem_u32(const void* p) {
    uint32_t a;
    asm("{ .reg .u64 t; cvta.to.shared.u64 t, %1; cvt.u32.u64 %0, t; }" : "=r"(a) : "l"(p));
    return a;
}
__device__ __forceinline__ void split_fp16(float v, __half& h, __half& l) {
    h = __float2half_rn(v);
    l = __float2half_rn(v - __half2float(h));
}
__device__ __forceinline__ void cp16(uint32_t sa, const void* ga) {
    asm volatile("cp.async.cg.shared.global [%0], [%1], 16;" :: "r"(sa), "l"(ga));
}
__device__ __forceinline__ void cp_commit() {
    asm volatile("cp.async.commit_group;" ::: "memory");
}
__device__ __forceinline__ void cp_wait1() {
    asm volatile("cp.async.wait_group 1;" ::: "memory");
}
__device__ __forceinline__ void ldsm_x4(uint32_t& r0, uint32_t& r1, uint32_t& r2, uint32_t& r3,
                                        uint32_t addr) {
    asm volatile("ldmatrix.sync.aligned.m8n8.x4.shared.b16 {%0,%1,%2,%3}, [%4];"
                 : "=r"(r0), "=r"(r1), "=r"(r2), "=r"(r3) : "r"(addr));
}
__device__ __forceinline__ void mma_fp16(float* d, const uint32_t* a, const uint32_t* b) {
    asm volatile(
        "mma.sync.aligned.m16n8k16.row.col.f32.f16.f16.f32 "
        "{%0,%1,%2,%3}, {%4,%5,%6,%7}, {%8,%9}, {%0,%1,%2,%3};"
        : "+f"(d[0]), "+f"(d[1]), "+f"(d[2]), "+f"(d[3])
        : "r"(a[0]), "r"(a[1]), "r"(a[2]), "r"(a[3]), "r"(b[0]), "r"(b[1]));
}
__device__ __forceinline__ int ioff(int k) { return ((k >> 4) << 5) + (k & 15); }

// ---- vectorized hi-only weight convert ------------------------------------
__device__ __forceinline__ void convw_unit(const float* __restrict__ W,
                                           __half* __restrict__ out,
                                           int K, long u)
{
    int kb16 = K >> 4;
    int n = (int)(u / kb16);
    int kb = (int)(u % kb16);
    const float4* src = reinterpret_cast<const float4*>(W + (size_t)n * K + (size_t)kb * 16);
    __half h[16];
#pragma unroll
    for (int q = 0; q < 4; q++) {
        float4 f = src[q];
        h[q * 4 + 0] = __float2half_rn(f.x);
        h[q * 4 + 1] = __float2half_rn(f.y);
        h[q * 4 + 2] = __float2half_rn(f.z);
        h[q * 4 + 3] = __float2half_rn(f.w);
    }
    uint4* d4 = reinterpret_cast<uint4*>(out + (size_t)n * K + (size_t)kb * 16);
    d4[0] = *reinterpret_cast<uint4*>(&h[0]);
    d4[1] = *reinterpret_cast<uint4*>(&h[8]);
}

// ---------------- mega prep: pool + weight converts + bn fold --------------
__global__ __launch_bounds__(256)
void prep_kernel(const float* __restrict__ p2, const float* __restrict__ p3,
                 const float* __restrict__ p4, const float* __restrict__ p5,
                 const float* __restrict__ rois,
                 const float* __restrict__ conv1_w, const float* __restrict__ conv2_w,
                 const float* __restrict__ logits_w, const float* __restrict__ bbox_w,
                 const float* __restrict__ cb1, const float* __restrict__ g1,
                 const float* __restrict__ b1, const float* __restrict__ m1,
                 const float* __restrict__ v1,
                 const float* __restrict__ cb2, const float* __restrict__ g2,
                 const float* __restrict__ b2, const float* __restrict__ m2,
                 const float* __restrict__ v2,
                 const float* __restrict__ lb, const float* __restrict__ bb)
{
    int bid = blockIdx.x;
    int tid = threadIdx.x;

    if (bid < PB_POOL) {
        int n = bid;
        float x1 = rois[4 * n + 0];
        float y1 = rois[4 * n + 1];
        float x2 = rois[4 * n + 2];
        float y2 = rois[4 * n + 3];

        float area = (y2 - y1) * (x2 - x1);
        float lv = rintf(log2f(sqrtf(area) / 224.0f)) + 4.0f;
        lv = fminf(fmaxf(lv, 2.0f), 5.0f);
        int lvl = (int)lv;

        const float* fmap;
        int H;
        if (lvl == 2)      { fmap = p2; H = 256; }
        else if (lvl == 3) { fmap = p3; H = 128; }
        else if (lvl == 4) { fmap = p4; H = 64;  }
        else               { fmap = p5; H = 32;  }

        float ny1 = y1 / IMG_DIM, nx1 = x1 / IMG_DIM;
        float ny2 = y2 / IMG_DIM, nx2 = x2 / IMG_DIM;

        __shared__ float s_ly[POOL], s_lx[POOL];
        __shared__ int   s_y0[POOL], s_y1[POOL], s_x0[POOL], s_x1[POOL];

        if (tid < POOL) {
            int i = tid;
            float t = (float)i / (float)(POOL - 1);
            float Hm1 = (float)(H - 1);
            float ys = ny1 * Hm1 + t * ((ny2 - ny1) * Hm1);
            float y0 = floorf(ys);
            s_ly[i] = ys - y0;
            int y0i = min(max((int)y0, 0), H - 1);
            s_y0[i] = y0i;
            s_y1[i] = min(y0i + 1, H - 1);
        } else if (tid < 2 * POOL) {
            int i = tid - POOL;
            float t = (float)i / (float)(POOL - 1);
            float Wm1 = (float)(H - 1);
            float xs = nx1 * Wm1 + t * ((nx2 - nx1) * Wm1);
            float x0 = floorf(xs);
            s_lx[i] = xs - x0;
            int x0i = min(max((int)x0, 0), H - 1);
            s_x0[i] = x0i;
            s_x1[i] = min(x0i + 1, H - 1);
        }
        __syncthreads();

        int HW = H * H;
        __half* arow = g_A1 + (size_t)n * K1I;

        for (int base = tid * 2; base < KDIM; base += 512) {
            __half hh[2], ll[2];
#pragma unroll
            for (int e = 0; e < 2; e++) {
                int idx = base + e;
                int c  = idx / (POOL * POOL);
                int p  = idx % (POOL * POOL);
                int iy = p / POOL;
                int ix = p % POOL;
                const float* f = fmap + (size_t)c * HW;
                int y0 = s_y0[iy], y1i = s_y1[iy];
                int x0 = s_x0[ix], x1i = s_x1[ix];
                float fy = s_ly[iy], fx = s_lx[ix];
                float v00 = __ldg(&f[y0  * H + x0 ]);
                float v01 = __ldg(&f[y0  * H + x1i]);
                float v10 = __ldg(&f[y1i * H + x0 ]);
                float v11 = __ldg(&f[y1i * H + x1i]);
                float v = v00 * (1.f - fy) * (1.f - fx)
                        + v01 * (1.f - fy) * fx
                        + v10 * fy * (1.f - fx)
                        + v11 * fy * fx;
                split_fp16(v, hh[e], ll[e]);
            }
            int o = ioff(base);
            __half2 hp; hp.x = hh[0]; hp.y = hh[1];
            __half2 lp; lp.x = ll[0]; lp.y = ll[1];
            *reinterpret_cast<__half2*>(&arow[o])      = hp;
            *reinterpret_cast<__half2*>(&arow[o + 16]) = lp;
        }
    } else if (bid < PB_CW2) {
        long units = (long)HID * (KDIM >> 4);
        long start = (long)(bid - PB_CW1) * 256 + tid;
        long stride = (long)NB_CW1 * 256;
        for (long u = start; u < units; u += stride)
            convw_unit(conv1_w, g_B1, KDIM, u);
    } else if (bid < PB_CW3) {
        long units = (long)HID * (HID >> 4);
        long start = (long)(bid - PB_CW2) * 256 + tid;
        long stride = (long)NB_CW2 * 256;
        for (long u = start; u < units; u += stride)
            convw_unit(conv2_w, g_B2, HID, u);
    } else if (bid < PB_BN) {
        long units = (long)NHEAD * (HID >> 4);
        long start = (long)(bid - PB_CW3) * 256 + tid;
        long stride = (long)NB_CW3 * 256;
        int kb16 = HID >> 4;
        for (long u = start; u < units; u += stride) {
            int r = (int)(u / kb16);
            long uu = u % kb16;
            if (r < NUM_CLASSES)
                convw_unit(logits_w, g_W3, HID, (long)r * kb16 + uu);
            else
                convw_unit(bbox_w, g_W3 + (size_t)NUM_CLASSES * HID, HID,
                           (long)(r - NUM_CLASSES) * kb16 + uu);
        }
    } else {
        int i = (bid - PB_BN) * 256 + tid;
        if (i < HID) {
            float s = g1[i] * rsqrtf(v1[i] + BN_EPS);
            g_scale1[i] = s;
            g_shift1[i] = (cb1[i] - m1[i]) * s + b1[i];
        } else if (i < 2 * HID) {
            int j = i - HID;
            float s = g2[j] * rsqrtf(v2[j] + BN_EPS);
            g_scale2[j] = s;
            g_shift2[j] = (cb2[j] - m2[j]) * s + b2[j];
        } else if (i < 2 * HID + NHEADP) {
            int j = i - 2 * HID;
            float v = 0.f;
            if (j < NUM_CLASSES)      v = lb[j];
            else if (j < NHEAD)       v = bb[j - NUM_CLASSES];
            g_shift3[j] = v;
        }
    }
}

// ---------------- fp16 HMMA GEMM, 2-pass comp, 3-stage ring ----------------
// Templated on M-tile. 128: 4x2 warps (GEMM1/2); 64: 2x4 warps (GEMM3).
// Iter = 16 logical k. Single __syncthreads per iteration (leading sync
// after cp_wait1 also orders buffer reuse: loads for i+2 target the buffer
// last read at iter i-1, and every warp passed this sync only after
// finishing iter i-1's ldsm reads).
__device__ __forceinline__ uint32_t sw_a(int row, int ch) {      // 64B rows
    return (uint32_t)(row * 64 + ((ch ^ ((row >> 1) & 3)) << 4));
}
__device__ __forceinline__ uint32_t sw_b(int row, int ch) {      // 32B rows
    return (uint32_t)(row * 32 + ((ch ^ ((row >> 2) & 1)) << 4));
}

template<int MT>
__device__ __forceinline__ void load_stage(uint32_t stg, const __half* A, const __half* B,
                                           int m0, int n0, int ldA, int K, int it, int tid)
{
#pragma unroll
    for (int j = 0; j < MT / 64; j++) {
        int u = tid + j * 256;
        int row = u >> 2;
        int ch = u & 3;
        cp16(stg + sw_a(row, ch),
             (const void*)(A + (size_t)(m0 + row) * ldA + it * 32 + ch * 8));
    }
    {
        int row = tid >> 1;
        int ch = tid & 1;
        cp16(stg + MT * 64 + sw_b(row, ch),
             (const void*)(B + (size_t)(n0 + row) * K + it * 16 + ch * 8));
    }
}

// mode 1: fp16 split out rows of K2I; mode 2: head -> d_out
template<int MT>
__global__ __launch_bounds__(256)
void gemm_hmma_kernel(const __half* __restrict__ A, const __half* __restrict__ B,
                      int K,
                      const float* __restrict__ scale, const float* __restrict__ shift,
                      float* __restrict__ Cf, __half* __restrict__ Cb, int mode)
{
    constexpr int WM = MT / 32;
    constexpr int WN = 8 / WM;
    constexpr int WCOLS = 128 / WN;
    constexpr int NT = WCOLS / 16;
    constexpr int NJ = WCOLS / 8;
    constexpr int STG = MT * 64 + 4096;

    __shared__ __align__(1024) uint8_t smem[3 * STG];

    int tid = threadIdx.x;
    int lane = tid & 31;
    int wid = tid >> 5;
    int wm = wid % WM;
    int wn = wid / WM;
    int m0 = blockIdx.y * MT;
    int n0 = blockIdx.x * 128;
    int ldA = 2 * K;

    uint32_t sb = smem_u32(smem);

    float acc[2][NJ][4];
#pragma unroll
    for (int i = 0; i < 2; i++)
#pragma unroll
        for (int j = 0; j < NJ; j++)
#pragma unroll
            for (int q = 0; q < 4; q++) acc[i][j][q] = 0.f;

    int nk = K / 16;

    load_stage<MT>(sb, A, B, m0, n0, ldA, K, 0, tid);
    cp_commit();
    load_stage<MT>(sb + STG, A, B, m0, n0, ldA, K, 1, tid);
    cp_commit();

    int arow = wm * 32 + (lane & 15);
    int ach  = lane >> 4;
    int brow = wn * WCOLS + (lane & 7) + ((lane & 16) ? 8 : 0);
    int bch  = (lane & 8) ? 1 : 0;

    uint32_t stg_of[3] = { sb, sb + STG, sb + 2u * STG };

    for (int i = 0; i < nk; i++) {
        cp_wait1();
        __syncthreads();
        int j = i + 2;
        if (j < nk)
            load_stage<MT>(stg_of[j % 3], A, B, m0, n0, ldA, K, j, tid);
        cp_commit();

        uint32_t st = stg_of[i % 3];
        uint32_t ah[2][4], al[2][4], bh[NJ][2];
#pragma unroll
        for (int mi = 0; mi < 2; mi++) {
            ldsm_x4(ah[mi][0], ah[mi][1], ah[mi][2], ah[mi][3],
                    st + sw_a(arow + mi * 16, ach));
            ldsm_x4(al[mi][0], al[mi][1], al[mi][2], al[mi][3],
                    st + sw_a(arow + mi * 16, ach + 2));
        }
#pragma unroll
        for (int nt = 0; nt < NT; nt++)
            ldsm_x4(bh[nt * 2][0], bh[nt * 2][1], bh[nt * 2 + 1][0], bh[nt * 2 + 1][1],
                    st + MT * 64 + sw_b(brow + nt * 16, bch));
#pragma unroll
        for (int mi = 0; mi < 2; mi++)
#pragma unroll
            for (int nj = 0; nj < NJ; nj++)
                mma_fp16(acc[mi][nj], ah[mi], bh[nj]);
#pragma unroll
        for (int mi = 0; mi < 2; mi++)
#pragma unroll
            for (int nj = 0; nj < NJ; nj++)
                mma_fp16(acc[mi][nj], al[mi], bh[nj]);
    }

#pragma unroll
    for (int mi = 0; mi < 2; mi++) {
        int rbase = m0 + wm * 32 + mi * 16 + (lane >> 2);
#pragma unroll
        for (int nj = 0; nj < NJ; nj++) {
            int c = n0 + wn * WCOLS + nj * 8 + (lane & 3) * 2;
#pragma unroll
            for (int half = 0; half < 2; half++) {
                int m = rbase + half * 8;
                if (m >= N_ROIS) continue;
                if (mode == 1) {
                    float v0 = fmaxf(acc[mi][nj][half * 2 + 0] * scale[c]     + shift[c],     0.f);
                    float v1 = fmaxf(acc[mi][nj][half * 2 + 1] * scale[c + 1] + shift[c + 1], 0.f);
                    __half h0, l0, h1, l1;
                    split_fp16(v0, h0, l0);
                    split_fp16(v1, h1, l1);
                    __half2 hh; hh.x = h0; hh.y = h1;
                    __half2 ll; ll.x = l0; ll.y = l1;
                    __half* crow = Cb + (size_t)m * K2I + ioff(c);
                    *reinterpret_cast<__half2*>(&crow[0])  = hh;
                    *reinterpret_cast<__half2*>(&crow[16]) = ll;
                } else {
#pragma unroll
                    for (int e = 0; e < 2; e++) {
                        int col = c + e;
                        if (col >= NHEAD) continue;
                        float v = acc[mi][nj][half * 2 + e] + shift[col];
                        if (col < NUM_CLASSES)
                            Cf[(size_t)m * NUM_CLASSES + col] = v;
                        else
                            Cf[(size_t)(2 * N_ROIS * NUM_CLASSES) +
                               (size_t)m * NBOX + (col - NUM_CLASSES)] = v;
                    }
                }
            }
        }
    }
}

// ---------------- softmax over logits -> probs -----------------------------
__global__ __launch_bounds__(128)
void softmax_kernel(float* __restrict__ out)
{
    int roi = blockIdx.x * 4 + (threadIdx.x >> 5);
    int lane = threadIdx.x & 31;
    if (roi >= N_ROIS) return;
    const float* lg = out + (size_t)roi * NUM_CLASSES;
    float* pr = out + (size_t)N_ROIS * NUM_CLASSES + (size_t)roi * NUM_CLASSES;

    float mx = -INFINITY;
    for (int k = lane; k < NUM_CLASSES; k += 32) mx = fmaxf(mx, lg[k]);
#pragma unroll
    for (int off = 16; off > 0; off >>= 1)
        mx = fmaxf(mx, __shfl_xor_sync(0xFFFFFFFFu, mx, off));

    float s = 0.f;
    for (int k = lane; k < NUM_CLASSES; k += 32) s += expf(lg[k] - mx);
#pragma unroll
    for (int off = 16; off > 0; off >>= 1)
        s += __shfl_xor_sync(0xFFFFFFFFu, s, off);

    float inv = 1.f / s;
    for (int k = lane; k < NUM_CLASSES; k += 32)
        pr[k] = expf(lg[k] - mx) * inv;
}

// ---------------- launch ---------------------------------------------------
extern "C" void kernel_launch(void* const* d_in, const int* in_sizes, int n_in,
                              void* d_out, int out_size)
{
    const float* p2       = (const float*)d_in[0];
    const float* p3       = (const float*)d_in[1];
    const float* p4       = (const float*)d_in[2];
    const float* p5       = (const float*)d_in[3];
    const float* rois     = (const float*)d_in[4];
    const float* conv1_w  = (const float*)d_in[5];
    const float* conv1_b  = (const float*)d_in[6];
    const float* bn1_g    = (const float*)d_in[7];
    const float* bn1_b    = (const float*)d_in[8];
    const float* bn1_m    = (const float*)d_in[9];
    const float* bn1_v    = (const float*)d_in[10];
    const float* conv2_w  = (const float*)d_in[11];
    const float* conv2_b  = (const float*)d_in[12];
    const float* bn2_g    = (const float*)d_in[13];
    const float* bn2_b    = (const float*)d_in[14];
    const float* bn2_m    = (const float*)d_in[15];
    const float* bn2_v    = (const float*)d_in[16];
    const float* logits_w = (const float*)d_in[17];
    const float* logits_b = (const float*)d_in[18];
    const float* bbox_w   = (const float*)d_in[19];
    const float* bbox_b   = (const float*)d_in[20];
    float* out = (float*)d_out;

    __half *a1, *b1, *a2, *b2, *a3, *w3;
    float *sc1, *sf1, *sc2, *sf2, *sf3;
    cudaGetSymbolAddress((void**)&a1, g_A1);
    cudaGetSymbolAddress((void**)&b1, g_B1);
    cudaGetSymbolAddress((void**)&a2, g_A2);
    cudaGetSymbolAddress((void**)&b2, g_B2);
    cudaGetSymbolAddress((void**)&a3, g_A3);
    cudaGetSymbolAddress((void**)&w3, g_W3);
    cudaGetSymbolAddress((void**)&sc1, g_scale1);
    cudaGetSymbolAddress((void**)&sf1, g_shift1);
    cudaGetSymbolAddress((void**)&sc2, g_scale2);
    cudaGetSymbolAddress((void**)&sf2, g_shift2);
    cudaGetSymbolAddress((void**)&sf3, g_shift3);

    prep_kernel<<<PREP_GRID, 256>>>(p2, p3, p4, p5, rois,
                                    conv1_w, conv2_w, logits_w, bbox_w,
                                    conv1_b, bn1_g, bn1_b, bn1_m, bn1_v,
                                    conv2_b, bn2_g, bn2_b, bn2_m, bn2_v,
                                    logits_b, bbox_b);

    {
        dim3 grid1(HID / 128, MPAD / 128);       // (8, 16)
        gemm_hmma_kernel<128><<<grid1, 256>>>(a1, b1, KDIM, sc1, sf1, nullptr, a2, 1);
        gemm_hmma_kernel<128><<<grid1, 256>>>(a2, b2, HID, sc2, sf2, nullptr, a3, 1);
        dim3 grid3(NHEADP / 128, MPAD / 64);     // (4, 32)
        gemm_hmma_kernel<64><<<grid3, 256>>>(a3, w3, HID, nullptr, sf3, out, nullptr, 2);
    }

    softmax_kernel<<<(N_ROIS + 3) / 4, 128>>>(out);
}

// round 17
// speedup vs baseline: 1.1567x; 1.0599x over previous
#include <cuda_runtime.h>
#include <cuda_fp16.h>
#include <math.h>
#include <stdint.h>

#define N_ROIS      2000
#define MPAD        2048
#define POOL        7
#define C_FEAT      256
#define KDIM        (C_FEAT * POOL * POOL)   // 12544
#define K1I         (2 * KDIM)
#define HID         1024
#define K2I         (2 * HID)
#define NUM_CLASSES 81
#define NBOX        (NUM_CLASSES * 4)
#define NHEAD       (NUM_CLASSES + NBOX)     // 405
#define NHEADP      512
#define BN_EPS      0.001f
#define IMG_DIM     1024.0f

// prep kernel block layout
#define PB_POOL     N_ROIS
#define NB_CW1      192
#define NB_CW2      24
#define NB_CW3      12
#define NB_BN       10
#define PB_CW1      (PB_POOL)
#define PB_CW2      (PB_CW1 + NB_CW1)
#define PB_CW3      (PB_CW2 + NB_CW2)
#define PB_BN       (PB_CW3 + NB_CW3)
#define PREP_GRID   (PB_BN + NB_BN)

// ---------------- scratch (device globals; zero-initialized) ---------------
__device__ __align__(128) __half g_A1[(size_t)MPAD * K1I];
__device__ __align__(128) __half g_B1[(size_t)HID * KDIM];
__device__ __align__(128) __half g_A2[(size_t)MPAD * K2I];
__device__ __align__(128) __half g_B2[(size_t)HID * HID];
__device__ __align__(128) __half g_A3[(size_t)MPAD * K2I];
__device__ __align__(128) __half g_W3[(size_t)NHEADP * HID];
__device__ float g_scale1[HID], g_shift1[HID];
__device__ float g_scale2[HID], g_shift2[HID];
__device__ float g_shift3[NHEADP];

// ---------------- helpers ---------------------------------------------------
__device__ __forceinline__ uint32_t smem_u32(const void* p) {
    uint32_t a;
    asm("{ .reg .u64 t; cvta.to.shared.u64 t, %1; cvt.u32.u64 %0, t; }" : "=r"(a) : "l"(p));
    return a;
}
__device__ __forceinline__ void split_fp16(float v, __half& h, __half& l) {
    h = __float2half_rn(v);
    l = __float2half_rn(v - __half2float(h));
}
__device__ __forceinline__ void cp16(uint32_t sa, const void* ga) {
    asm volatile("cp.async.cg.shared.global [%0], [%1], 16;" :: "r"(sa), "l"(ga));
}
__device__ __forceinline__ void cp_commit() {
    asm volatile("cp.async.commit_group;" ::: "memory");
}
__device__ __forceinline__ void cp_wait1() {
    asm volatile("cp.async.wait_group 1;" ::: "memory");
}
__device__ __forceinline__ void ldsm_x4(uint32_t& r0, uint32_t& r1, uint32_t& r2, uint32_t& r3,
                                        uint32_t addr) {
    asm volatile("ldmatrix.sync.aligned.m8n8.x4.shared.b16 {%0,%1,%2,%3}, [%4];"
                 : "=r"(r0), "=r"(r1), "=r"(r2), "=r"(r3) : "r"(addr));
}
__device__ __forceinline__ void mma_fp16(float* d, const uint32_t* a, const uint32_t* b) {
    asm volatile(
        "mma.sync.aligned.m16n8k16.row.col.f32.f16.f16.f32 "
        "{%0,%1,%2,%3}, {%4,%5,%6,%7}, {%8,%9}, {%0,%1,%2,%3};"
        : "+f"(d[0]), "+f"(d[1]), "+f"(d[2]), "+f"(d[3])
        : "r"(a[0]), "r"(a[1]), "r"(a[2]), "r"(a[3]), "r"(b[0]), "r"(b[1]));
}
__device__ __forceinline__ int ioff(int k) { return ((k >> 4) << 5) + (k & 15); }

// ---- vectorized hi-only weight convert ------------------------------------
__device__ __forceinline__ void convw_unit(const float* __restrict__ W,
                                           __half* __restrict__ out,
                                           int K, long u)
{
    int kb16 = K >> 4;
    int n = (int)(u / kb16);
    int kb = (int)(u % kb16);
    const float4* src = reinterpret_cast<const float4*>(W + (size_t)n * K + (size_t)kb * 16);
    __half h[16];
#pragma unroll
    for (int q = 0; q < 4; q++) {
        float4 f = src[q];
        h[q * 4 + 0] = __float2half_rn(f.x);
        h[q * 4 + 1] = __float2half_rn(f.y);
        h[q * 4 + 2] = __float2half_rn(f.z);
        h[q * 4 + 3] = __float2half_rn(f.w);
    }
    uint4* d4 = reinterpret_cast<uint4*>(out + (size_t)n * K + (size_t)kb * 16);
    d4[0] = *reinterpret_cast<uint4*>(&h[0]);
    d4[1] = *reinterpret_cast<uint4*>(&h[8]);
}

// ---------------- mega prep: pool + weight converts + bn fold --------------
__global__ __launch_bounds__(256)
void prep_kernel(const float* __restrict__ p2, const float* __restrict__ p3,
                 const float* __restrict__ p4, const float* __restrict__ p5,
                 const float* __restrict__ rois,
                 const float* __restrict__ conv1_w, const float* __restrict__ conv2_w,
                 const float* __restrict__ logits_w, const float* __restrict__ bbox_w,
                 const float* __restrict__ cb1, const float* __restrict__ g1,
                 const float* __restrict__ b1, const float* __restrict__ m1,
                 const float* __restrict__ v1,
                 const float* __restrict__ cb2, const float* __restrict__ g2,
                 const float* __restrict__ b2, const float* __restrict__ m2,
                 const float* __restrict__ v2,
                 const float* __restrict__ lb, const float* __restrict__ bb)
{
    int bid = blockIdx.x;
    int tid = threadIdx.x;

    if (bid < PB_POOL) {
        int n = bid;
        float x1 = rois[4 * n + 0];
        float y1 = rois[4 * n + 1];
        float x2 = rois[4 * n + 2];
        float y2 = rois[4 * n + 3];

        float area = (y2 - y1) * (x2 - x1);
        float lv = rintf(log2f(sqrtf(area) / 224.0f)) + 4.0f;
        lv = fminf(fmaxf(lv, 2.0f), 5.0f);
        int lvl = (int)lv;

        const float* fmap;
        int H;
        if (lvl == 2)      { fmap = p2; H = 256; }
        else if (lvl == 3) { fmap = p3; H = 128; }
        else if (lvl == 4) { fmap = p4; H = 64;  }
        else               { fmap = p5; H = 32;  }

        float ny1 = y1 / IMG_DIM, nx1 = x1 / IMG_DIM;
        float ny2 = y2 / IMG_DIM, nx2 = x2 / IMG_DIM;

        __shared__ float s_ly[POOL], s_lx[POOL];
        __shared__ int   s_y0[POOL], s_y1[POOL], s_x0[POOL], s_x1[POOL];

        if (tid < POOL) {
            int i = tid;
            float t = (float)i / (float)(POOL - 1);
            float Hm1 = (float)(H - 1);
            float ys = ny1 * Hm1 + t * ((ny2 - ny1) * Hm1);
            float y0 = floorf(ys);
            s_ly[i] = ys - y0;
            int y0i = min(max((int)y0, 0), H - 1);
            s_y0[i] = y0i;
            s_y1[i] = min(y0i + 1, H - 1);
        } else if (tid < 2 * POOL) {
            int i = tid - POOL;
            float t = (float)i / (float)(POOL - 1);
            float Wm1 = (float)(H - 1);
            float xs = nx1 * Wm1 + t * ((nx2 - nx1) * Wm1);
            float x0 = floorf(xs);
            s_lx[i] = xs - x0;
            int x0i = min(max((int)x0, 0), H - 1);
            s_x0[i] = x0i;
            s_x1[i] = min(x0i + 1, H - 1);
        }
        __syncthreads();

        int HW = H * H;
        __half* arow = g_A1 + (size_t)n * K1I;

        for (int base = tid * 2; base < KDIM; base += 512) {
            __half hh[2], ll[2];
#pragma unroll
            for (int e = 0; e < 2; e++) {
                int idx = base + e;
                int c  = idx / (POOL * POOL);
                int p  = idx % (POOL * POOL);
                int iy = p / POOL;
                int ix = p % POOL;
                const float* f = fmap + (size_t)c * HW;
                int y0 = s_y0[iy], y1i = s_y1[iy];
                int x0 = s_x0[ix], x1i = s_x1[ix];
                float fy = s_ly[iy], fx = s_lx[ix];
                float v00 = __ldg(&f[y0  * H + x0 ]);
                float v01 = __ldg(&f[y0  * H + x1i]);
                float v10 = __ldg(&f[y1i * H + x0 ]);
                float v11 = __ldg(&f[y1i * H + x1i]);
                float v = v00 * (1.f - fy) * (1.f - fx)
                        + v01 * (1.f - fy) * fx
                        + v10 * fy * (1.f - fx)
                        + v11 * fy * fx;
                split_fp16(v, hh[e], ll[e]);
            }
            int o = ioff(base);
            __half2 hp; hp.x = hh[0]; hp.y = hh[1];
            __half2 lp; lp.x = ll[0]; lp.y = ll[1];
            *reinterpret_cast<__half2*>(&arow[o])      = hp;
            *reinterpret_cast<__half2*>(&arow[o + 16]) = lp;
        }
    } else if (bid < PB_CW2) {
        long units = (long)HID * (KDIM >> 4);
        long start = (long)(bid - PB_CW1) * 256 + tid;
        long stride = (long)NB_CW1 * 256;
        for (long u = start; u < units; u += stride)
            convw_unit(conv1_w, g_B1, KDIM, u);
    } else if (bid < PB_CW3) {
        long units = (long)HID * (HID >> 4);
        long start = (long)(bid - PB_CW2) * 256 + tid;
        long stride = (long)NB_CW2 * 256;
        for (long u = start; u < units; u += stride)
            convw_unit(conv2_w, g_B2, HID, u);
    } else if (bid < PB_BN) {
        long units = (long)NHEAD * (HID >> 4);
        long start = (long)(bid - PB_CW3) * 256 + tid;
        long stride = (long)NB_CW3 * 256;
        int kb16 = HID >> 4;
        for (long u = start; u < units; u += stride) {
            int r = (int)(u / kb16);
            long uu = u % kb16;
            if (r < NUM_CLASSES)
                convw_unit(logits_w, g_W3, HID, (long)r * kb16 + uu);
            else
                convw_unit(bbox_w, g_W3 + (size_t)NUM_CLASSES * HID, HID,
                           (long)(r - NUM_CLASSES) * kb16 + uu);
        }
    } else {
        int i = (bid - PB_BN) * 256 + tid;
        if (i < HID) {
            float s = g1[i] * rsqrtf(v1[i] + BN_EPS);
            g_scale1[i] = s;
            g_shift1[i] = (cb1[i] - m1[i]) * s + b1[i];
        } else if (i < 2 * HID) {
            int j = i - HID;
            float s = g2[j] * rsqrtf(v2[j] + BN_EPS);
            g_scale2[j] = s;
            g_shift2[j] = (cb2[j] - m2[j]) * s + b2[j];
        } else if (i < 2 * HID + NHEADP) {
            int j = i - 2 * HID;
            float v = 0.f;
            if (j < NUM_CLASSES)      v = lb[j];
            else if (j < NHEAD)       v = bb[j - NUM_CLASSES];
            g_shift3[j] = v;
        }
    }
}

// ---------------- fp16 HMMA GEMM, 2-pass comp, 3-stage ring ----------------
// Templated on M-tile. 128: 4x2 warps; 64: 2x4 warps.
// Single __syncthreads per iteration (leading sync after cp_wait1 also
// orders buffer reuse across warps).
__device__ __forceinline__ uint32_t sw_a(int row, int ch) {      // 64B rows
    return (uint32_t)(row * 64 + ((ch ^ ((row >> 1) & 3)) << 4));
}
__device__ __forceinline__ uint32_t sw_b(int row, int ch) {      // 32B rows
    return (uint32_t)(row * 32 + ((ch ^ ((row >> 2) & 1)) << 4));
}

template<int MT>
__device__ __forceinline__ void load_stage(uint32_t stg, const __half* A, const __half* B,
                                           int m0, int n0, int ldA, int K, int it, int tid)
{
#pragma unroll
    for (int j = 0; j < MT / 64; j++) {
        int u = tid + j * 256;
        int row = u >> 2;
        int ch = u & 3;
        cp16(stg + sw_a(row, ch),
             (const void*)(A + (size_t)(m0 + row) * ldA + it * 32 + ch * 8));
    }
    {
        int row = tid >> 1;
        int ch = tid & 1;
        cp16(stg + MT * 64 + sw_b(row, ch),
             (const void*)(B + (size_t)(n0 + row) * K + it * 16 + ch * 8));
    }
}

// mode 1: fp16 split out rows of K2I; mode 2: head -> d_out
template<int MT>
__global__ __launch_bounds__(256)
void gemm_hmma_kernel(const __half* __restrict__ A, const __half* __restrict__ B,
                      int K,
                      const float* __restrict__ scale, const float* __restrict__ shift,
                      float* __restrict__ Cf, __half* __restrict__ Cb, int mode)
{
    constexpr int WM = MT / 32;
    constexpr int WN = 8 / WM;
    constexpr int WCOLS = 128 / WN;
    constexpr int NT = WCOLS / 16;
    constexpr int NJ = WCOLS / 8;
    constexpr int STG = MT * 64 + 4096;

    __shared__ __align__(1024) uint8_t smem[3 * STG];

    int tid = threadIdx.x;
    int lane = tid & 31;
    int wid = tid >> 5;
    int wm = wid % WM;
    int wn = wid / WM;
    int m0 = blockIdx.y * MT;
    int n0 = blockIdx.x * 128;
    int ldA = 2 * K;

    uint32_t sb = smem_u32(smem);

    float acc[2][NJ][4];
#pragma unroll
    for (int i = 0; i < 2; i++)
#pragma unroll
        for (int j = 0; j < NJ; j++)
#pragma unroll
            for (int q = 0; q < 4; q++) acc[i][j][q] = 0.f;

    int nk = K / 16;

    load_stage<MT>(sb, A, B, m0, n0, ldA, K, 0, tid);
    cp_commit();
    load_stage<MT>(sb + STG, A, B, m0, n0, ldA, K, 1, tid);
    cp_commit();

    int arow = wm * 32 + (lane & 15);
    int ach  = lane >> 4;
    int brow = wn * WCOLS + (lane & 7) + ((lane & 16) ? 8 : 0);
    int bch  = (lane & 8) ? 1 : 0;

    uint32_t stg_of[3] = { sb, sb + STG, sb + 2u * STG };

    for (int i = 0; i < nk; i++) {
        cp_wait1();
        __syncthreads();
        int j = i + 2;
        if (j < nk)
            load_stage<MT>(stg_of[j % 3], A, B, m0, n0, ldA, K, j, tid);
        cp_commit();

        uint32_t st = stg_of[i % 3];
        uint32_t ah[2][4], al[2][4], bh[NJ][2];
#pragma unroll
        for (int mi = 0; mi < 2; mi++) {
            ldsm_x4(ah[mi][0], ah[mi][1], ah[mi][2], ah[mi][3],
                    st + sw_a(arow + mi * 16, ach));
            ldsm_x4(al[mi][0], al[mi][1], al[mi][2], al[mi][3],
                    st + sw_a(arow + mi * 16, ach + 2));
        }
#pragma unroll
        for (int nt = 0; nt < NT; nt++)
            ldsm_x4(bh[nt * 2][0], bh[nt * 2][1], bh[nt * 2 + 1][0], bh[nt * 2 + 1][1],
                    st + MT * 64 + sw_b(brow + nt * 16, bch));
#pragma unroll
        for (int mi = 0; mi < 2; mi++)
#pragma unroll
            for (int nj = 0; nj < NJ; nj++)
                mma_fp16(acc[mi][nj], ah[mi], bh[nj]);
#pragma unroll
        for (int mi = 0; mi < 2; mi++)
#pragma unroll
            for (int nj = 0; nj < NJ; nj++)
                mma_fp16(acc[mi][nj], al[mi], bh[nj]);
    }

#pragma unroll
    for (int mi = 0; mi < 2; mi++) {
        int rbase = m0 + wm * 32 + mi * 16 + (lane >> 2);
#pragma unroll
        for (int nj = 0; nj < NJ; nj++) {
            int c = n0 + wn * WCOLS + nj * 8 + (lane & 3) * 2;
#pragma unroll
            for (int half = 0; half < 2; half++) {
                int m = rbase + half * 8;
                if (m >= N_ROIS) continue;
                if (mode == 1) {
                    float v0 = fmaxf(acc[mi][nj][half * 2 + 0] * scale[c]     + shift[c],     0.f);
                    float v1 = fmaxf(acc[mi][nj][half * 2 + 1] * scale[c + 1] + shift[c + 1], 0.f);
                    __half h0, l0, h1, l1;
                    split_fp16(v0, h0, l0);
                    split_fp16(v1, h1, l1);
                    __half2 hh; hh.x = h0; hh.y = h1;
                    __half2 ll; ll.x = l0; ll.y = l1;
                    __half* crow = Cb + (size_t)m * K2I + ioff(c);
                    *reinterpret_cast<__half2*>(&crow[0])  = hh;
                    *reinterpret_cast<__half2*>(&crow[16]) = ll;
                } else {
#pragma unroll
                    for (int e = 0; e < 2; e++) {
                        int col = c + e;
                        if (col >= NHEAD) continue;
                        float v = acc[mi][nj][half * 2 + e] + shift[col];
                        if (col < NUM_CLASSES)
                            Cf[(size_t)m * NUM_CLASSES + col] = v;
                        else
                            Cf[(size_t)(2 * N_ROIS * NUM_CLASSES) +
                               (size_t)m * NBOX + (col - NUM_CLASSES)] = v;
                    }
                }
            }
        }
    }
}

// ---------------- softmax over logits -> probs -----------------------------
__global__ __launch_bounds__(128)
void softmax_kernel(float* __restrict__ out)
{
    int roi = blockIdx.x * 4 + (threadIdx.x >> 5);
    int lane = threadIdx.x & 31;
    if (roi >= N_ROIS) return;
    const float* lg = out + (size_t)roi * NUM_CLASSES;
    float* pr = out + (size_t)N_ROIS * NUM_CLASSES + (size_t)roi * NUM_CLASSES;

    float mx = -INFINITY;
    for (int k = lane; k < NUM_CLASSES; k += 32) mx = fmaxf(mx, lg[k]);
#pragma unroll
    for (int off = 16; off > 0; off >>= 1)
        mx = fmaxf(mx, __shfl_xor_sync(0xFFFFFFFFu, mx, off));

    float s = 0.f;
    for (int k = lane; k < NUM_CLASSES; k += 32) s += expf(lg[k] - mx);
#pragma unroll
    for (int off = 16; off > 0; off >>= 1)
        s += __shfl_xor_sync(0xFFFFFFFFu, s, off);

    float inv = 1.f / s;
    for (int k = lane; k < NUM_CLASSES; k += 32)
        pr[k] = expf(lg[k] - mx) * inv;
}

// ---------------- launch ---------------------------------------------------
extern "C" void kernel_launch(void* const* d_in, const int* in_sizes, int n_in,
                              void* d_out, int out_size)
{
    const float* p2       = (const float*)d_in[0];
    const float* p3       = (const float*)d_in[1];
    const float* p4       = (const float*)d_in[2];
    const float* p5       = (const float*)d_in[3];
    const float* rois     = (const float*)d_in[4];
    const float* conv1_w  = (const float*)d_in[5];
    const float* conv1_b  = (const float*)d_in[6];
    const float* bn1_g    = (const float*)d_in[7];
    const float* bn1_b    = (const float*)d_in[8];
    const float* bn1_m    = (const float*)d_in[9];
    const float* bn1_v    = (const float*)d_in[10];
    const float* conv2_w  = (const float*)d_in[11];
    const float* conv2_b  = (const float*)d_in[12];
    const float* bn2_g    = (const float*)d_in[13];
    const float* bn2_b    = (const float*)d_in[14];
    const float* bn2_m    = (const float*)d_in[15];
    const float* bn2_v    = (const float*)d_in[16];
    const float* logits_w = (const float*)d_in[17];
    const float* logits_b = (const float*)d_in[18];
    const float* bbox_w   = (const float*)d_in[19];
    const float* bbox_b   = (const float*)d_in[20];
    float* out = (float*)d_out;

    __half *a1, *b1, *a2, *b2, *a3, *w3;
    float *sc1, *sf1, *sc2, *sf2, *sf3;
    cudaGetSymbolAddress((void**)&a1, g_A1);
    cudaGetSymbolAddress((void**)&b1, g_B1);
    cudaGetSymbolAddress((void**)&a2, g_A2);
    cudaGetSymbolAddress((void**)&b2, g_B2);
    cudaGetSymbolAddress((void**)&a3, g_A3);
    cudaGetSymbolAddress((void**)&w3, g_W3);
    cudaGetSymbolAddress((void**)&sc1, g_scale1);
    cudaGetSymbolAddress((void**)&sf1, g_shift1);
    cudaGetSymbolAddress((void**)&sc2, g_scale2);
    cudaGetSymbolAddress((void**)&sf2, g_shift2);
    cudaGetSymbolAddress((void**)&sf3, g_shift3);

    prep_kernel<<<PREP_GRID, 256>>>(p2, p3, p4, p5, rois,
                                    conv1_w, conv2_w, logits_w, bbox_w,
                                    conv1_b, bn1_g, bn1_b, bn1_m, bn1_v,
                                    conv2_b, bn2_g, bn2_b, bn2_m, bn2_v,
                                    logits_b, bbox_b);

    {
        dim3 grid1(HID / 128, MPAD / 64);        // (8, 32) = 256 CTAs
        gemm_hmma_kernel<64><<<grid1, 256>>>(a1, b1, KDIM, sc1, sf1, nullptr, a2, 1);
        dim3 grid2(HID / 128, MPAD / 128);       // (8, 16)
        gemm_hmma_kernel<128><<<grid2, 256>>>(a2, b2, HID, sc2, sf2, nullptr, a3, 1);
        dim3 grid3(NHEADP / 128, MPAD / 64);     // (4, 32)
        gemm_hmma_kernel<64><<<grid3, 256>>>(a3, w3, HID, nullptr, sf3, out, nullptr, 2);
    }

    softmax_kernel<<<(N_ROIS + 3) / 4, 128>>>(out);
}